// round 1
// baseline (speedup 1.0000x reference)
#include <cuda_runtime.h>
#include <cuda_bf16.h>
#include <cstdint>

// Sobel gradient magnitude, zero-padded, on [B=8, C=64, H=256, W=256] fp32.
// out = sqrt(gv^2 + gh^2 + 1e-6), gv = x[i+1,j]-x[i-1,j], gh = x[i,j+1]-x[i,j-1].
//
// One thread per float4 along W. All dims are powers of two:
//   W4 = 64 float4 per row, H = 256 rows per plane.
// Vertical neighbors: float4 loads at +/- one row (L2-resident reuse).
// Horizontal neighbors: center float4 + 2 scalar edge loads.

static constexpr int W      = 256;
static constexpr int H      = 256;
static constexpr int W4     = W / 4;        // 64
static constexpr int LOG_W4 = 6;

__global__ __launch_bounds__(256)
void sobel_grad_mag_kernel(const float4* __restrict__ in,
                           float4* __restrict__ out,
                           int n4)
{
    int i = blockIdx.x * blockDim.x + threadIdx.x;
    if (i >= n4) return;

    int col4 = i & (W4 - 1);
    int row  = (i >> LOG_W4) & (H - 1);

    float4 c = in[i];

    float4 up, dn;
    if (row == 0) {
        up = make_float4(0.f, 0.f, 0.f, 0.f);
    } else {
        up = in[i - W4];
    }
    if (row == H - 1) {
        dn = make_float4(0.f, 0.f, 0.f, 0.f);
    } else {
        dn = in[i + W4];
    }

    const float* sc = reinterpret_cast<const float*>(in);
    float left  = (col4 == 0)      ? 0.f : sc[i * 4 - 1];
    float right = (col4 == W4 - 1) ? 0.f : sc[i * 4 + 4];

    // vertical gradient: down - up
    float gv0 = dn.x - up.x;
    float gv1 = dn.y - up.y;
    float gv2 = dn.z - up.z;
    float gv3 = dn.w - up.w;

    // horizontal gradient: right neighbor - left neighbor
    float gh0 = c.y   - left;
    float gh1 = c.z   - c.x;
    float gh2 = c.w   - c.y;
    float gh3 = right - c.z;

    const float EPS = 1e-6f;
    float4 r;
    r.x = sqrtf(fmaf(gv0, gv0, fmaf(gh0, gh0, EPS)));
    r.y = sqrtf(fmaf(gv1, gv1, fmaf(gh1, gh1, EPS)));
    r.z = sqrtf(fmaf(gv2, gv2, fmaf(gh2, gh2, EPS)));
    r.w = sqrtf(fmaf(gv3, gv3, fmaf(gh3, gh3, EPS)));

    out[i] = r;
}

extern "C" void kernel_launch(void* const* d_in, const int* in_sizes, int n_in,
                              void* d_out, int out_size)
{
    const float4* x = reinterpret_cast<const float4*>(d_in[0]);
    float4* o       = reinterpret_cast<float4*>(d_out);

    int n4 = out_size / 4;  // 33,554,432 / 4 = 8,388,608 float4 outputs
    int threads = 256;
    int blocks  = (n4 + threads - 1) / threads;

    sobel_grad_mag_kernel<<<blocks, threads>>>(x, o, n4);
}

// round 2
// speedup vs baseline: 1.0610x; 1.0610x over previous
#include <cuda_runtime.h>
#include <cuda_bf16.h>
#include <cstdint>

// Sobel gradient magnitude, zero-padded, on [B=8, C=64, H=256, W=256] fp32.
// out = sqrt(gv^2 + gh^2 + 1e-6), gv = x[i+1,j]-x[i-1,j], gh = x[i,j+1]-x[i,j-1].
//
// Round 2: 4 rows per thread (vertical register blocking) + warp-shuffle for
// horizontal neighbors (scalar edge loads only on lanes 0/31) + streaming stores.
//
// Layout: W4 = 64 float4 per row, H = 256 rows, plane = 2^14 float4.
// Thread t: col4 = t & 63, row-quad rq = (t>>6) & 63, plane = t>>12.
// Warp = 32 consecutive t -> 32 consecutive col4 (never wraps a row).

static constexpr int W4 = 64;

__global__ __launch_bounds__(256)
void sobel_grad_mag_r4(const float4* __restrict__ in,
                       float4* __restrict__ out,
                       int nthreads)
{
    int t = blockIdx.x * blockDim.x + threadIdx.x;
    if (t >= nthreads) return;

    const int lane = threadIdx.x & 31;
    const int col4 = t & (W4 - 1);
    const int rq   = (t >> 6) & 63;                 // row-quad index, rows 4*rq..4*rq+3
    const int i0   = ((t >> 12) << 14) | (rq << 8) | col4;

    const float4 zero = make_float4(0.f, 0.f, 0.f, 0.f);

    // 6 row vectors cover 4 output rows
    float4 rv[6];
    rv[0] = (rq == 0)  ? zero : __ldg(&in[i0 - W4]);
    rv[1] = __ldg(&in[i0]);
    rv[2] = __ldg(&in[i0 + 1 * W4]);
    rv[3] = __ldg(&in[i0 + 2 * W4]);
    rv[4] = __ldg(&in[i0 + 3 * W4]);
    rv[5] = (rq == 63) ? zero : __ldg(&in[i0 + 4 * W4]);

    const float* sc = reinterpret_cast<const float*>(in);
    const float EPS = 1e-6f;

    #pragma unroll
    for (int k = 0; k < 4; k++) {
        const float4 up = rv[k];
        const float4 c  = rv[k + 1];
        const float4 dn = rv[k + 2];

        // horizontal neighbors from adjacent lanes (same row vector)
        float l = __shfl_up_sync(0xffffffffu, c.w, 1);
        float r = __shfl_down_sync(0xffffffffu, c.x, 1);
        if (lane == 0)
            l = (col4 == 0) ? 0.f : sc[(size_t)(i0 + k * W4) * 4 - 1];
        if (lane == 31)
            r = (col4 == W4 - 1) ? 0.f : sc[(size_t)(i0 + k * W4) * 4 + 4];

        const float gv0 = dn.x - up.x;
        const float gv1 = dn.y - up.y;
        const float gv2 = dn.z - up.z;
        const float gv3 = dn.w - up.w;

        const float gh0 = c.y - l;
        const float gh1 = c.z - c.x;
        const float gh2 = c.w - c.y;
        const float gh3 = r   - c.z;

        float4 res;
        res.x = sqrtf(fmaf(gv0, gv0, fmaf(gh0, gh0, EPS)));
        res.y = sqrtf(fmaf(gv1, gv1, fmaf(gh1, gh1, EPS)));
        res.z = sqrtf(fmaf(gv2, gv2, fmaf(gh2, gh2, EPS)));
        res.w = sqrtf(fmaf(gv3, gv3, fmaf(gh3, gh3, EPS)));

        __stcs(&out[i0 + k * W4], res);
    }
}

extern "C" void kernel_launch(void* const* d_in, const int* in_sizes, int n_in,
                              void* d_out, int out_size)
{
    const float4* x = reinterpret_cast<const float4*>(d_in[0]);
    float4* o       = reinterpret_cast<float4*>(d_out);

    // total float4 outputs = out_size/4; each thread produces 4 of them
    int nthreads = out_size / 16;   // 2,097,152
    int threads  = 256;
    int blocks   = (nthreads + threads - 1) / threads;

    sobel_grad_mag_r4<<<blocks, threads>>>(x, o, nthreads);
}